// round 4
// baseline (speedup 1.0000x reference)
#include <cuda_runtime.h>

// out[b,i,j,f] = x[b,i,f] * y[b,j,f]; second half of d_out = 0.75 * first half.
// x,y: [B,3,128] fp32. Mandatory traffic: 307MB read + 922MB write.
// Uses Blackwell 256-bit vector ld/st (LDG.E.256 / STG.E.256): one thread per
// 8-float f-group; every warp store instruction covers 1024B = 8 full sectors.

__device__ __forceinline__ void ldg256(float v[8], const float* p) {
    asm("ld.global.v8.f32 {%0,%1,%2,%3,%4,%5,%6,%7}, [%8];"
        : "=f"(v[0]), "=f"(v[1]), "=f"(v[2]), "=f"(v[3]),
          "=f"(v[4]), "=f"(v[5]), "=f"(v[6]), "=f"(v[7])
        : "l"(p));
}

__device__ __forceinline__ void stg256(float* p, const float v[8]) {
    asm volatile("st.global.v8.f32 [%0], {%1,%2,%3,%4,%5,%6,%7,%8};"
        :: "l"(p),
           "f"(v[0]), "f"(v[1]), "f"(v[2]), "f"(v[3]),
           "f"(v[4]), "f"(v[5]), "f"(v[6]), "f"(v[7])
        : "memory");
}

__global__ __launch_bounds__(256)
void tp_kernel(const float* __restrict__ x,
               const float* __restrict__ y,
               float* __restrict__ out,
               int B)
{
    int idx = blockIdx.x * blockDim.x + threadIdx.x;
    int total = B * 16;                 // 16 eight-float groups of f per b
    if (idx >= total) return;

    int b  = idx >> 4;
    int f8 = (idx & 15) * 8;

    const float* xp = x + (size_t)b * 384 + f8;   // [b][i][f], row = 128 floats
    const float* yp = y + (size_t)b * 384 + f8;

    float xv[3][8], yv[3][8];
#pragma unroll
    for (int i = 0; i < 3; i++) {
        ldg256(xv[i], xp + i * 128);
        ldg256(yv[i], yp + i * 128);
    }

    const size_t half = (size_t)B * 1152;         // floats in first output half
    float* op = out + (size_t)b * 1152 + f8;

#pragma unroll
    for (int i = 0; i < 3; i++) {
#pragma unroll
        for (int j = 0; j < 3; j++) {
            float p[8], q[8];
#pragma unroll
            for (int k = 0; k < 8; k++) {
                p[k] = xv[i][k] * yv[j][k];
                q[k] = 0.75f * p[k];
            }
            size_t o = (size_t)(i * 3 + j) * 128;
            stg256(op + o, p);
            stg256(op + half + o, q);
        }
    }
}

extern "C" void kernel_launch(void* const* d_in, const int* in_sizes, int n_in,
                              void* d_out, int out_size)
{
    const float* x = (const float*)d_in[0];
    const float* y = (const float*)d_in[1];
    float* out = (float*)d_out;

    int B = in_sizes[0] / (3 * 128);    // 100000
    int total = B * 16;
    int threads = 256;
    int blocks = (total + threads - 1) / threads;
    tp_kernel<<<blocks, threads>>>(x, y, out, B);
}

// round 6
// speedup vs baseline: 1.0311x; 1.0311x over previous
#include <cuda_runtime.h>

// out[b,i,j,f] = x[b,i,f] * y[b,j,f]; second half of d_out = 0.75 * first half.
// Store-centric layout: one thread per float4 of the first output half.
// idx = (b*9 + i*3 + j)*32 + f4  ->  store is out[idx] (perfectly linear).
// Only 2 loads + 2 stores per thread, tiny register count -> max occupancy,
// maximizing outstanding store sectors at the DRAM controller.
// x/y re-read 3x across threads but reuse distance is tiny -> L1/L2 hits;
// DRAM read traffic stays at the mandatory 307MB.

__global__ __launch_bounds__(256)
void tp_kernel(const float4* __restrict__ x,
               const float4* __restrict__ y,
               float4* __restrict__ out,
               unsigned total, unsigned halfi)
{
    unsigned idx = blockIdx.x * blockDim.x + threadIdx.x;
    if (idx >= total) return;

    unsigned f4 = idx & 31u;
    unsigned g  = idx >> 5;          // b*9 + ij
    unsigned b  = g / 9u;            // compiler-generated reciprocal mul
    unsigned ij = g - b * 9u;
    unsigned i  = ij / 3u;
    unsigned j  = ij - i * 3u;

    float4 xv = x[(b * 3u + i) * 32u + f4];
    float4 yv = y[(b * 3u + j) * 32u + f4];

    float4 p;
    p.x = xv.x * yv.x;
    p.y = xv.y * yv.y;
    p.z = xv.z * yv.z;
    p.w = xv.w * yv.w;
    out[idx] = p;

    float4 q;
    q.x = 0.75f * p.x;
    q.y = 0.75f * p.y;
    q.z = 0.75f * p.z;
    q.w = 0.75f * p.w;
    out[halfi + idx] = q;
}

extern "C" void kernel_launch(void* const* d_in, const int* in_sizes, int n_in,
                              void* d_out, int out_size)
{
    const float4* x = (const float4*)d_in[0];
    const float4* y = (const float4*)d_in[1];
    float4* out = (float4*)d_out;

    int B = in_sizes[0] / (3 * 128);        // 100000
    unsigned total = (unsigned)B * 9u * 32u; // float4 elements in first half
    int threads = 256;
    int blocks = (int)((total + threads - 1) / threads);
    tp_kernel<<<blocks, threads>>>(x, y, out, total, total);
}